// round 6
// baseline (speedup 1.0000x reference)
#include <cuda_runtime.h>
#include <cuda_bf16.h>
#include <cstdint>

#define CIN   128
#define COUT  128
#define KHW   9
#define NB    (CIN*COUT*KHW)   // 147456
#define ZD    256
#define BATCH 32
#define HW    32
#define HW2   (HW*HW)

// ---------------- scratch (device globals; no allocs allowed) ----------------
__device__ __align__(1024) float          g_Wk[BATCH * NB];                 // fp32 (b,s,f,uv)
__device__ __align__(1024) __nv_bfloat16  g_W2hi[BATCH * 9 * 128 * 128];    // (b,uv,f,s)
__device__ __align__(1024) __nv_bfloat16  g_W2lo[BATCH * 9 * 128 * 128];
__device__ __align__(1024) __nv_bfloat16  g_xhi[BATCH * 34 * 36 * 128];     // (b,row,col,s) padded, pad stays 0
__device__ __align__(1024) __nv_bfloat16  g_xlo[BATCH * 34 * 36 * 128];

// ---------------- helpers ----------------
__device__ __forceinline__ uint32_t smem_u32(const void* p) {
    uint32_t a;
    asm("{ .reg .u64 t; cvta.to.shared.u64 t, %1; cvt.u32.u64 %0, t; }" : "=r"(a) : "l"(p));
    return a;
}
__device__ __forceinline__ void cp16(uint32_t dst, const void* src) {
    asm volatile("cp.async.cg.shared.global [%0], [%1], 16;" :: "r"(dst), "l"(src) : "memory");
}
#define CP_COMMIT() asm volatile("cp.async.commit_group;" ::: "memory")

__device__ __forceinline__ void ldsm4(uint32_t* r, uint32_t a) {
    asm volatile("ldmatrix.sync.aligned.m8n8.x4.shared.b16 {%0,%1,%2,%3}, [%4];"
                 : "=r"(r[0]), "=r"(r[1]), "=r"(r[2]), "=r"(r[3]) : "r"(a));
}
__device__ __forceinline__ void ldsm4t(uint32_t* r, uint32_t a) {
    asm volatile("ldmatrix.sync.aligned.m8n8.x4.trans.shared.b16 {%0,%1,%2,%3}, [%4];"
                 : "=r"(r[0]), "=r"(r[1]), "=r"(r[2]), "=r"(r[3]) : "r"(a));
}
__device__ __forceinline__ void mma16816(float* d, const uint32_t* a, const uint32_t* b) {
    asm volatile(
        "mma.sync.aligned.m16n8k16.row.col.f32.bf16.bf16.f32 "
        "{%0,%1,%2,%3}, {%4,%5,%6,%7}, {%8,%9}, {%0,%1,%2,%3};"
        : "+f"(d[0]), "+f"(d[1]), "+f"(d[2]), "+f"(d[3])
        : "r"(a[0]), "r"(a[1]), "r"(a[2]), "r"(a[3]), "r"(b[0]), "r"(b[1]));
}
__device__ __forceinline__ uint32_t pack_hi(float a, float b) {
    __nv_bfloat162 p = __floats2bfloat162_rn(a, b);
    return *reinterpret_cast<uint32_t*>(&p);
}
__device__ __forceinline__ uint32_t pack_lo(float a, float b, uint32_t hi) {
    __nv_bfloat162 h = *reinterpret_cast<__nv_bfloat162*>(&hi);
    __nv_bfloat162 p = __floats2bfloat162_rn(a - __bfloat162float(h.x),
                                             b - __bfloat162float(h.y));
    return *reinterpret_cast<uint32_t*>(&p);
}

// ===========================================================================
// Kernel A (v2): hyper GEMM, LDG->reg-convert->STS (no fp32 smem staging).
//   M=32, K=256, N=128 per CTA (1152 CTAs), 256 thr, 2 CTAs/SM.
//   B dbl-buffered [k32][n128] bf16 hi/lo; A (z) resident split-bf16.
// smem: A_HI 0 (16896) | A_LO 16896 | B bufs @33792: 2 x (BH 8704 + BL 8704)
// ===========================================================================
#define HP_PITCH 528
#define HP_BP    272
#define HP_RAHI  0
#define HP_RALO  16896
#define HP_RB    33792
#define HP_BUF   17408
#define HP_SMEM  68608

__global__ __launch_bounds__(256, 2) void hyper_mma_kernel(
    const float* __restrict__ z, const float* __restrict__ dw,
    const float* __restrict__ db, const float* __restrict__ gamma,
    const float* __restrict__ beta)
{
    extern __shared__ char hs[];
    const uint32_t sb = smem_u32(hs);
    const int tid = threadIdx.x, wid = tid >> 5, lane = tid & 31;
    const int n0 = blockIdx.x * 128;
    const int wn0 = wid * 16;

    // A (z) -> split bf16 smem [m=32][k=256], pitch 528B
    {
        const int m = tid >> 3, k0 = (tid & 7) * 32;
        const float4* zsrc = reinterpret_cast<const float4*>(z + m * ZD + k0);
        char* rowh = hs + HP_RAHI + m * HP_PITCH + k0 * 2;
        char* rowl = hs + HP_RALO + m * HP_PITCH + k0 * 2;
#pragma unroll
        for (int j = 0; j < 8; j++) {
            float4 v = zsrc[j];
            uint32_t h01 = pack_hi(v.x, v.y), h23 = pack_hi(v.z, v.w);
            uint32_t l01 = pack_lo(v.x, v.y, h01), l23 = pack_lo(v.z, v.w, h23);
            *reinterpret_cast<uint2*>(rowh + j * 8) = make_uint2(h01, h23);
            *reinterpret_cast<uint2*>(rowl + j * 8) = make_uint2(l01, l23);
        }
    }

    // dw loader: thread owns k-row (tid>>3) within each 32-row stage, 16 n.
    const int krow = tid >> 3, nseg = (tid & 7) * 16;
    const float* dwp = dw + (size_t)krow * NB + n0 + nseg;
    char* bdst_h = hs + HP_RB + krow * HP_BP + nseg * 2;

    float4 cur[4], nxt[4];
#pragma unroll
    for (int j = 0; j < 4; j++)
        cur[j] = *reinterpret_cast<const float4*>(dwp + j * 4);

    float d[2][2][4];
#pragma unroll
    for (int mt = 0; mt < 2; mt++)
#pragma unroll
        for (int nt = 0; nt < 2; nt++)
#pragma unroll
            for (int e = 0; e < 4; e++) d[mt][nt][e] = 0.0f;

    const uint32_t aoff = (uint32_t)((lane & 15) * HP_PITCH + (lane >> 4) * 16);
    const uint32_t boff = (uint32_t)((((lane >> 3) & 1) * 8 + (lane & 7)) * HP_BP
                                     + (wn0 + (lane >> 4) * 8) * 2);

    for (int s = 0; s < 8; s++) {
        if (s < 7) {
            const float* p = dwp + (size_t)(s + 1) * 32 * NB;
#pragma unroll
            for (int j = 0; j < 4; j++)
                nxt[j] = *reinterpret_cast<const float4*>(p + j * 4);
        }
        // convert cur -> B buffer (s&1)
        {
            char* bh = bdst_h + (s & 1) * HP_BUF;
            char* bl = bh + 8704;
#pragma unroll
            for (int j = 0; j < 4; j++) {
                float4 v = cur[j];
                uint32_t h01 = pack_hi(v.x, v.y), h23 = pack_hi(v.z, v.w);
                uint32_t l01 = pack_lo(v.x, v.y, h01), l23 = pack_lo(v.z, v.w, h23);
                *reinterpret_cast<uint2*>(bh + j * 8) = make_uint2(h01, h23);
                *reinterpret_cast<uint2*>(bl + j * 8) = make_uint2(l01, l23);
            }
        }
        __syncthreads();

        const uint32_t bbase = sb + HP_RB + (uint32_t)(s & 1) * HP_BUF;
#pragma unroll
        for (int kk = 0; kk < 2; kk++) {
            uint32_t ah[2][4], al[2][4], bh[4], bl[4];
            const uint32_t akoff = (uint32_t)(s * 64 + kk * 32);
#pragma unroll
            for (int mt = 0; mt < 2; mt++) {
                ldsm4(ah[mt], sb + HP_RAHI + mt * 16 * HP_PITCH + akoff + aoff);
                ldsm4(al[mt], sb + HP_RALO + mt * 16 * HP_PITCH + akoff + aoff);
            }
            ldsm4t(bh, bbase + kk * 16 * HP_BP + boff);
            ldsm4t(bl, bbase + 8704 + kk * 16 * HP_BP + boff);
#pragma unroll
            for (int mt = 0; mt < 2; mt++)
#pragma unroll
                for (int nt = 0; nt < 2; nt++) {
                    mma16816(d[mt][nt], ah[mt], &bh[nt * 2]);
                    mma16816(d[mt][nt], ah[mt], &bl[nt * 2]);
                    mma16816(d[mt][nt], al[mt], &bh[nt * 2]);
                }
        }
#pragma unroll
        for (int j = 0; j < 4; j++) cur[j] = nxt[j];
    }

    // ---- epilogue: relu + BN over 32 batch rows (warp-local) ----
    const int jc = n0 + wn0 + 2 * (lane & 3);
    float2 db2[2], g2[2], bt2[2];
#pragma unroll
    for (int nt = 0; nt < 2; nt++) {
        db2[nt] = *reinterpret_cast<const float2*>(db + jc + nt * 8);
        g2[nt]  = *reinterpret_cast<const float2*>(gamma + jc + nt * 8);
        bt2[nt] = *reinterpret_cast<const float2*>(beta + jc + nt * 8);
    }
#pragma unroll
    for (int mt = 0; mt < 2; mt++)
#pragma unroll
        for (int nt = 0; nt < 2; nt++) {
            d[mt][nt][0] = fmaxf(d[mt][nt][0] + db2[nt].x, 0.0f);
            d[mt][nt][1] = fmaxf(d[mt][nt][1] + db2[nt].y, 0.0f);
            d[mt][nt][2] = fmaxf(d[mt][nt][2] + db2[nt].x, 0.0f);
            d[mt][nt][3] = fmaxf(d[mt][nt][3] + db2[nt].y, 0.0f);
        }

    float sm[2][2], sq[2][2];
#pragma unroll
    for (int nt = 0; nt < 2; nt++)
#pragma unroll
        for (int c = 0; c < 2; c++) {
            float s1 = d[0][nt][c] + d[0][nt][c + 2] + d[1][nt][c] + d[1][nt][c + 2];
            float q1 = d[0][nt][c] * d[0][nt][c] + d[0][nt][c + 2] * d[0][nt][c + 2]
                     + d[1][nt][c] * d[1][nt][c] + d[1][nt][c + 2] * d[1][nt][c + 2];
#pragma unroll
            for (int o = 4; o < 32; o <<= 1) {
                s1 += __shfl_xor_sync(0xffffffffu, s1, o);
                q1 += __shfl_xor_sync(0xffffffffu, q1, o);
            }
            sm[nt][c] = s1 * (1.0f / 32.0f);
            float var = fmaxf(q1 * (1.0f / 32.0f) - sm[nt][c] * sm[nt][c], 0.0f);
            float gm = (c == 0) ? ((nt == 0) ? g2[0].x : g2[1].x)
                                : ((nt == 0) ? g2[0].y : g2[1].y);
            sq[nt][c] = gm / (sqrtf(var) + 1e-6f);
        }

    const int g = lane >> 2;
#pragma unroll
    for (int mt = 0; mt < 2; mt++)
#pragma unroll
        for (int nt = 0; nt < 2; nt++) {
            const int j = jc + nt * 8;
            float2 o0 = make_float2((d[mt][nt][0] - sm[nt][0]) * sq[nt][0] + bt2[nt].x,
                                    (d[mt][nt][1] - sm[nt][1]) * sq[nt][1] + bt2[nt].y);
            float2 o1 = make_float2((d[mt][nt][2] - sm[nt][0]) * sq[nt][0] + bt2[nt].x,
                                    (d[mt][nt][3] - sm[nt][1]) * sq[nt][1] + bt2[nt].y);
            *reinterpret_cast<float2*>(g_Wk + (size_t)(mt * 16 + g) * NB + j) = o0;
            *reinterpret_cast<float2*>(g_Wk + (size_t)(mt * 16 + g + 8) * NB + j) = o1;
        }
}

// ===========================================================================
// Kernel W: transpose + bf16-split W: (b,s,f,uv) fp32 -> (b,uv,f,s) hi/lo
// ===========================================================================
__global__ __launch_bounds__(256) void wtrans_kernel()
{
    __shared__ float sWk[9224];  // pitch 1153 per s_local
    const int b = blockIdx.y, sblk = blockIdx.x, tid = threadIdx.x;
    const float* src = g_Wk + (size_t)b * NB + (size_t)sblk * 9216;
    for (int i = tid; i < 9216; i += 256) {
        int sl = i / 1152;
        sWk[i + sl] = src[i];
    }
    __syncthreads();
    for (int t = tid; t < 9216; t += 256) {
        int uv = t >> 10, f = (t >> 3) & 127, sl = t & 7;
        float v = sWk[sl * 1153 + f * 9 + uv];
        __nv_bfloat16 h = __float2bfloat16(v);
        __nv_bfloat16 l = __float2bfloat16(v - __bfloat162float(h));
        size_t o = (((size_t)(b * 9 + uv) * 128) + f) * 128 + sblk * 8 + sl;
        g_W2hi[o] = h;
        g_W2lo[o] = l;
    }
}

// ===========================================================================
// Kernel X: x -> padded channel-last split-bf16 (b, row 34, col 36, s 128)
// ===========================================================================
__global__ __launch_bounds__(256) void xprep_kernel(const float* __restrict__ x)
{
    __shared__ float sX[128 * 33];
    const int b = blockIdx.y, p = blockIdx.x, tid = threadIdx.x;
    for (int i = tid; i < 4096; i += 256) {
        int s = i >> 5, q = i & 31;
        sX[s * 33 + q] = x[(((size_t)(b * 128 + s)) * 32 + p) * 32 + q];
    }
    __syncthreads();
    for (int i = tid; i < 4096; i += 256) {
        int s = i & 127, q = i >> 7;
        float v = sX[s * 33 + q];
        __nv_bfloat16 h = __float2bfloat16(v);
        __nv_bfloat16 l = __float2bfloat16(v - __bfloat162float(h));
        size_t o = (((size_t)b * 34 + (p + 1)) * 36 + (q + 1)) * 128 + s;
        g_xhi[o] = h;
        g_xlo[o] = l;
    }
}

// ===========================================================================
// Kernel C (v2): conv GEMM, 256 thr, N=128 px, k-chunk 32 (36 stages),
// buffers 2 x 40KB -> 2 CTAs/SM, grid 256.
// per-buffer: Ah@0 10240 | Al@10240 | Bh@20480 | Bl@30720  (pitch 80B)
// ===========================================================================
#define CPITCH 80
#define CBUF   40960
#define CSMEM  81920

__global__ __launch_bounds__(256, 2) void conv_mma_kernel(
    const float* __restrict__ xin,
    const float* __restrict__ bias,
    float* __restrict__ out)
{
    extern __shared__ char smem[];
    const uint32_t sb = smem_u32(smem);
    const int tid = threadIdx.x, wid = tid >> 5, lane = tid & 31;
    const int b = blockIdx.y, pb = blockIdx.x;     // pixel rows pb*4..pb*4+3
    const int f0 = (wid & 3) * 32;
    const int px0 = (wid >> 2) * 64;

    float d[2][8][4];
#pragma unroll
    for (int i = 0; i < 2; i++)
#pragma unroll
        for (int j = 0; j < 8; j++)
#pragma unroll
            for (int e = 0; e < 4; e++) d[i][j][e] = 0.0f;

    const uint32_t aoff = (uint32_t)((lane & 15) * CPITCH + (lane >> 4) * 16);
    const uint32_t boff = (uint32_t)(((lane & 7) + ((lane >> 4) << 3)) * CPITCH + ((lane >> 3) & 1) * 16);

    auto issue_stage = [&](int st) {
        const int uv = st >> 2, c = st & 3;
        const int u = uv / 3, v = uv - 3 * u;
        const uint32_t base = sb + (uint32_t)(st & 1) * CBUF;
        // A: 1024 cp16 (128 f x 4 segs x 2 halves)
#pragma unroll
        for (int i = 0; i < 4; i++) {
            int c2 = i * 256 + tid;
            int half = c2 >> 9, rem = c2 & 511, row = rem >> 2, seg = rem & 3;
            const __nv_bfloat16* src =
                (half ? g_W2lo : g_W2hi) +
                (((size_t)(b * 9 + uv) * 128 + row) * 128 + c * 32 + seg * 8);
            cp16(base + half * 10240 + row * CPITCH + seg * 16, src);
        }
        // B: 1024 cp16 (128 px x 4 segs x 2 halves)
#pragma unroll
        for (int i = 0; i < 4; i++) {
            int c2 = i * 256 + tid;
            int half = c2 >> 9, rem = c2 & 511, px = rem >> 2, seg = rem & 3;
            int prow = pb * 4 + (px >> 5), pcol = px & 31;
            const __nv_bfloat16* src =
                (half ? g_xlo : g_xhi) +
                (((size_t)(b * 34 + prow + u) * 36 + (pcol + v)) * 128 + c * 32 + seg * 8);
            cp16(base + 20480 + half * 10240 + px * CPITCH + seg * 16, src);
        }
        CP_COMMIT();
    };

    issue_stage(0);
    issue_stage(1);

    for (int st = 0; st < 36; st++) {
        if (st < 35) asm volatile("cp.async.wait_group 1;" ::: "memory");
        else         asm volatile("cp.async.wait_group 0;" ::: "memory");
        __syncthreads();

        const uint32_t base = sb + (uint32_t)(st & 1) * CBUF;
        const uint32_t baseAh = base, baseAl = base + 10240;
        const uint32_t baseBh = base + 20480, baseBl = base + 30720;

#pragma unroll
        for (int kk = 0; kk < 2; kk++) {
            const uint32_t ko = (uint32_t)kk * 32;
            uint32_t ah[2][4], al[2][4], bf[4][4];
#pragma unroll
            for (int i = 0; i < 2; i++) {
                ldsm4(ah[i], baseAh + (f0 + i * 16) * CPITCH + ko + aoff);
                ldsm4(al[i], baseAl + (f0 + i * 16) * CPITCH + ko + aoff);
            }
#pragma unroll
            for (int p = 0; p < 4; p++)
                ldsm4(bf[p], baseBh + (px0 + p * 16) * CPITCH + ko + boff);
#pragma unroll
            for (int i = 0; i < 2; i++)
#pragma unroll
                for (int t = 0; t < 8; t++)
                    mma16816(d[i][t], ah[i], &bf[t >> 1][(t & 1) * 2]);
#pragma unroll
            for (int i = 0; i < 2; i++)
#pragma unroll
                for (int t = 0; t < 8; t++)
                    mma16816(d[i][t], al[i], &bf[t >> 1][(t & 1) * 2]);
#pragma unroll
            for (int p = 0; p < 4; p++)
                ldsm4(bf[p], baseBl + (px0 + p * 16) * CPITCH + ko + boff);
#pragma unroll
            for (int i = 0; i < 2; i++)
#pragma unroll
                for (int t = 0; t < 8; t++)
                    mma16816(d[i][t], ah[i], &bf[t >> 1][(t & 1) * 2]);
        }
        __syncthreads();
        if (st + 2 < 36) issue_stage(st + 2);
    }

    // ---- epilogue: + residual + bias ----
    const int g = lane >> 2, tc = lane & 3;
#pragma unroll
    for (int i = 0; i < 2; i++) {
        const int fr0 = f0 + i * 16 + g;
        const float bv0 = __ldg(&bias[fr0]);
        const float bv1 = __ldg(&bias[fr0 + 8]);
#pragma unroll
        for (int j = 0; j < 8; j++) {
            const int pix = pb * 128 + px0 + j * 8 + tc * 2;
            {
                size_t o = ((size_t)(b * 128 + fr0)) * 1024 + pix;
                float2 xr = *reinterpret_cast<const float2*>(xin + o);
                float2 w = make_float2(d[i][j][0] + xr.x + bv0,
                                       d[i][j][1] + xr.y + bv0);
                *reinterpret_cast<float2*>(out + o) = w;
            }
            {
                size_t o = ((size_t)(b * 128 + fr0 + 8)) * 1024 + pix;
                float2 xr = *reinterpret_cast<const float2*>(xin + o);
                float2 w = make_float2(d[i][j][2] + xr.x + bv1,
                                       d[i][j][3] + xr.y + bv1);
                *reinterpret_cast<float2*>(out + o) = w;
            }
        }
    }
}

// ===========================================================================
extern "C" void kernel_launch(void* const* d_in, const int* in_sizes, int n_in,
                              void* d_out, int out_size)
{
    (void)in_sizes; (void)n_in; (void)out_size;
    const float* x     = (const float*)d_in[0];
    const float* z     = (const float*)d_in[1];
    const float* dw    = (const float*)d_in[2];
    const float* db    = (const float*)d_in[3];
    const float* gamma = (const float*)d_in[4];
    const float* beta  = (const float*)d_in[5];
    const float* bconv = (const float*)d_in[6];
    float* out = (float*)d_out;

    cudaFuncSetAttribute(hyper_mma_kernel,
                         cudaFuncAttributeMaxDynamicSharedMemorySize, HP_SMEM);
    cudaFuncSetAttribute(conv_mma_kernel,
                         cudaFuncAttributeMaxDynamicSharedMemorySize, CSMEM);

    hyper_mma_kernel<<<NB / 128, 256, HP_SMEM>>>(z, dw, db, gamma, beta);
    xprep_kernel<<<dim3(32, BATCH), 256>>>(x);
    wtrans_kernel<<<dim3(16, BATCH), 256>>>();
    conv_mma_kernel<<<dim3(8, BATCH), 256, CSMEM>>>(x, bconv, out);
}

// round 7
// speedup vs baseline: 1.1871x; 1.1871x over previous
#include <cuda_runtime.h>
#include <cuda_bf16.h>
#include <cstdint>

#define CIN   128
#define COUT  128
#define KHW   9
#define NB    (CIN*COUT*KHW)   // 147456
#define ZD    256
#define BATCH 32
#define HW    32
#define HW2   (HW*HW)

// ---------------- scratch (device globals; no allocs allowed) ----------------
__device__ __align__(1024) float          g_Wk[BATCH * NB];                 // fp32 (b,s,f,uv)
__device__ __align__(1024) __nv_bfloat16  g_W2hi[BATCH * 9 * 128 * 128];    // (b,uv,f,s)
__device__ __align__(1024) __nv_bfloat16  g_W2lo[BATCH * 9 * 128 * 128];
__device__ __align__(1024) __nv_bfloat16  g_xhi[BATCH * 34 * 36 * 128];     // (b,row,col,s) padded, pad stays 0
__device__ __align__(1024) __nv_bfloat16  g_xlo[BATCH * 34 * 36 * 128];

// ---------------- helpers ----------------
__device__ __forceinline__ uint32_t smem_u32(const void* p) {
    uint32_t a;
    asm("{ .reg .u64 t; cvta.to.shared.u64 t, %1; cvt.u32.u64 %0, t; }" : "=r"(a) : "l"(p));
    return a;
}
__device__ __forceinline__ void cp16(uint32_t dst, const void* src) {
    asm volatile("cp.async.cg.shared.global [%0], [%1], 16;" :: "r"(dst), "l"(src) : "memory");
}
#define CP_COMMIT() asm volatile("cp.async.commit_group;" ::: "memory")

__device__ __forceinline__ void ldsm4(uint32_t* r, uint32_t a) {
    asm volatile("ldmatrix.sync.aligned.m8n8.x4.shared.b16 {%0,%1,%2,%3}, [%4];"
                 : "=r"(r[0]), "=r"(r[1]), "=r"(r[2]), "=r"(r[3]) : "r"(a));
}
__device__ __forceinline__ void ldsm4t(uint32_t* r, uint32_t a) {
    asm volatile("ldmatrix.sync.aligned.m8n8.x4.trans.shared.b16 {%0,%1,%2,%3}, [%4];"
                 : "=r"(r[0]), "=r"(r[1]), "=r"(r[2]), "=r"(r[3]) : "r"(a));
}
__device__ __forceinline__ void mma16816(float* d, const uint32_t* a, const uint32_t* b) {
    asm volatile(
        "mma.sync.aligned.m16n8k16.row.col.f32.bf16.bf16.f32 "
        "{%0,%1,%2,%3}, {%4,%5,%6,%7}, {%8,%9}, {%0,%1,%2,%3};"
        : "+f"(d[0]), "+f"(d[1]), "+f"(d[2]), "+f"(d[3])
        : "r"(a[0]), "r"(a[1]), "r"(a[2]), "r"(a[3]), "r"(b[0]), "r"(b[1]));
}
__device__ __forceinline__ uint32_t pack_hi(float a, float b) {
    __nv_bfloat162 p = __floats2bfloat162_rn(a, b);
    return *reinterpret_cast<uint32_t*>(&p);
}
__device__ __forceinline__ uint32_t pack_lo(float a, float b, uint32_t hi) {
    __nv_bfloat162 h = *reinterpret_cast<__nv_bfloat162*>(&hi);
    __nv_bfloat162 p = __floats2bfloat162_rn(a - __bfloat162float(h.x),
                                             b - __bfloat162float(h.y));
    return *reinterpret_cast<uint32_t*>(&p);
}

// ===========================================================================
// Kernel A: hyper GEMM + fused BN (R5 proven version)
// ===========================================================================
#define HP_PITCH 528
#define HP_F32P  1040
#define HP_RAHI  0
#define HP_RALO  16896
#define HP_RF32  33792
#define HP_RBH   100352
#define HP_RBL   117248
#define HP_SMEM  134144

__global__ __launch_bounds__(512, 1) void hyper_mma_kernel(
    const float* __restrict__ z, const float* __restrict__ dw,
    const float* __restrict__ db, const float* __restrict__ gamma,
    const float* __restrict__ beta)
{
    extern __shared__ char hs[];
    const uint32_t sb = smem_u32(hs);
    const int tid = threadIdx.x, wid = tid >> 5, lane = tid & 31;
    const int n0 = blockIdx.x * 256;
    const int wn0 = wid * 16;

    auto issue = [&](int s) {
#pragma unroll
        for (int i = 0; i < 4; i++) {
            int chunk = tid + i * 512;
            int k = chunk >> 6, seg = chunk & 63;
            cp16(sb + HP_RF32 + (s & 1) * 33280 + k * HP_F32P + seg * 16,
                 dw + (size_t)(s * 32 + k) * NB + n0 + seg * 4);
        }
        CP_COMMIT();
    };
    issue(0); CP_COMMIT();
    issue(1);

    {
        const int m = tid >> 4, k0 = (tid & 15) * 16;
        const float4* zsrc = reinterpret_cast<const float4*>(z + m * ZD + k0);
        char* rowh = hs + HP_RAHI + m * HP_PITCH + k0 * 2;
        char* rowl = hs + HP_RALO + m * HP_PITCH + k0 * 2;
#pragma unroll
        for (int j = 0; j < 4; j++) {
            float4 v = zsrc[j];
            uint32_t h01 = pack_hi(v.x, v.y), h23 = pack_hi(v.z, v.w);
            uint32_t l01 = pack_lo(v.x, v.y, h01), l23 = pack_lo(v.z, v.w, h23);
            *reinterpret_cast<uint2*>(rowh + j * 8) = make_uint2(h01, h23);
            *reinterpret_cast<uint2*>(rowl + j * 8) = make_uint2(l01, l23);
        }
    }

    float d[2][2][4];
#pragma unroll
    for (int mt = 0; mt < 2; mt++)
#pragma unroll
        for (int nt = 0; nt < 2; nt++)
#pragma unroll
            for (int e = 0; e < 4; e++) d[mt][nt][e] = 0.0f;

    const uint32_t aoff = (uint32_t)((lane & 15) * HP_PITCH + (lane >> 4) * 16);
    const uint32_t boff = (uint32_t)((((lane >> 3) & 1) * 8 + (lane & 7)) * HP_PITCH
                                     + (wn0 + (lane >> 4) * 8) * 2);

    for (int s = 0; s < 8; s++) {
        if (s < 6) asm volatile("cp.async.wait_group 1;" ::: "memory");
        else       asm volatile("cp.async.wait_group 0;" ::: "memory");
        __syncthreads();

        {
            const int k = tid >> 4;
            const float* frow = reinterpret_cast<const float*>(
                hs + HP_RF32 + (s & 1) * 33280 + k * HP_F32P);
            char* bh = hs + HP_RBH + k * HP_PITCH;
            char* bl = hs + HP_RBL + k * HP_PITCH;
#pragma unroll
            for (int j = 0; j < 4; j++) {
                int n4 = (tid & 15) * 4 + j * 64;
                float4 v = *reinterpret_cast<const float4*>(frow + n4);
                uint32_t h01 = pack_hi(v.x, v.y), h23 = pack_hi(v.z, v.w);
                uint32_t l01 = pack_lo(v.x, v.y, h01), l23 = pack_lo(v.z, v.w, h23);
                *reinterpret_cast<uint2*>(bh + n4 * 2) = make_uint2(h01, h23);
                *reinterpret_cast<uint2*>(bl + n4 * 2) = make_uint2(l01, l23);
            }
        }
        __syncthreads();
        if (s + 2 < 8) issue(s + 2);

#pragma unroll
        for (int kk = 0; kk < 2; kk++) {
            uint32_t ah[2][4], al[2][4], bh[4], bl[4];
            const uint32_t akoff = (uint32_t)(s * 64 + kk * 32);
#pragma unroll
            for (int mt = 0; mt < 2; mt++) {
                ldsm4(ah[mt], sb + HP_RAHI + mt * 16 * HP_PITCH + akoff + aoff);
                ldsm4(al[mt], sb + HP_RALO + mt * 16 * HP_PITCH + akoff + aoff);
            }
            ldsm4t(bh, sb + HP_RBH + kk * 16 * HP_PITCH + boff);
            ldsm4t(bl, sb + HP_RBL + kk * 16 * HP_PITCH + boff);
#pragma unroll
            for (int mt = 0; mt < 2; mt++)
#pragma unroll
                for (int nt = 0; nt < 2; nt++) {
                    mma16816(d[mt][nt], ah[mt], &bh[nt * 2]);
                    mma16816(d[mt][nt], ah[mt], &bl[nt * 2]);
                    mma16816(d[mt][nt], al[mt], &bh[nt * 2]);
                }
        }
    }

    const int jc = n0 + wn0 + 2 * (lane & 3);
    float2 db2[2], g2[2], bt2[2];
#pragma unroll
    for (int nt = 0; nt < 2; nt++) {
        db2[nt] = *reinterpret_cast<const float2*>(db + jc + nt * 8);
        g2[nt]  = *reinterpret_cast<const float2*>(gamma + jc + nt * 8);
        bt2[nt] = *reinterpret_cast<const float2*>(beta + jc + nt * 8);
    }
#pragma unroll
    for (int mt = 0; mt < 2; mt++)
#pragma unroll
        for (int nt = 0; nt < 2; nt++) {
            d[mt][nt][0] = fmaxf(d[mt][nt][0] + db2[nt].x, 0.0f);
            d[mt][nt][1] = fmaxf(d[mt][nt][1] + db2[nt].y, 0.0f);
            d[mt][nt][2] = fmaxf(d[mt][nt][2] + db2[nt].x, 0.0f);
            d[mt][nt][3] = fmaxf(d[mt][nt][3] + db2[nt].y, 0.0f);
        }

    float sm[2][2], sq[2][2];
#pragma unroll
    for (int nt = 0; nt < 2; nt++)
#pragma unroll
        for (int c = 0; c < 2; c++) {
            float s1 = d[0][nt][c] + d[0][nt][c + 2] + d[1][nt][c] + d[1][nt][c + 2];
            float q1 = d[0][nt][c] * d[0][nt][c] + d[0][nt][c + 2] * d[0][nt][c + 2]
                     + d[1][nt][c] * d[1][nt][c] + d[1][nt][c + 2] * d[1][nt][c + 2];
#pragma unroll
            for (int o = 4; o < 32; o <<= 1) {
                s1 += __shfl_xor_sync(0xffffffffu, s1, o);
                q1 += __shfl_xor_sync(0xffffffffu, q1, o);
            }
            sm[nt][c] = s1 * (1.0f / 32.0f);
            float var = fmaxf(q1 * (1.0f / 32.0f) - sm[nt][c] * sm[nt][c], 0.0f);
            float gm = (c == 0) ? ((nt == 0) ? g2[0].x : g2[1].x)
                                : ((nt == 0) ? g2[0].y : g2[1].y);
            sq[nt][c] = gm / (sqrtf(var) + 1e-6f);
        }

    const int g = lane >> 2;
#pragma unroll
    for (int mt = 0; mt < 2; mt++)
#pragma unroll
        for (int nt = 0; nt < 2; nt++) {
            const int j = jc + nt * 8;
            float2 o0 = make_float2((d[mt][nt][0] - sm[nt][0]) * sq[nt][0] + bt2[nt].x,
                                    (d[mt][nt][1] - sm[nt][1]) * sq[nt][1] + bt2[nt].y);
            float2 o1 = make_float2((d[mt][nt][2] - sm[nt][0]) * sq[nt][0] + bt2[nt].x,
                                    (d[mt][nt][3] - sm[nt][1]) * sq[nt][1] + bt2[nt].y);
            *reinterpret_cast<float2*>(g_Wk + (size_t)(mt * 16 + g) * NB + j) = o0;
            *reinterpret_cast<float2*>(g_Wk + (size_t)(mt * 16 + g + 8) * NB + j) = o1;
        }
}

// ===========================================================================
// Kernel W: transpose + bf16-split W: (b,s,f,uv) fp32 -> (b,uv,f,s) hi/lo
// ===========================================================================
__global__ __launch_bounds__(256) void wtrans_kernel()
{
    __shared__ float sWk[9224];
    const int b = blockIdx.y, sblk = blockIdx.x, tid = threadIdx.x;
    const float* src = g_Wk + (size_t)b * NB + (size_t)sblk * 9216;
    for (int i = tid; i < 9216; i += 256) {
        int sl = i / 1152;
        sWk[i + sl] = src[i];
    }
    __syncthreads();
    for (int t = tid; t < 9216; t += 256) {
        int uv = t >> 10, f = (t >> 3) & 127, sl = t & 7;
        float v = sWk[sl * 1153 + f * 9 + uv];
        __nv_bfloat16 h = __float2bfloat16(v);
        __nv_bfloat16 l = __float2bfloat16(v - __bfloat162float(h));
        size_t o = (((size_t)(b * 9 + uv) * 128) + f) * 128 + sblk * 8 + sl;
        g_W2hi[o] = h;
        g_W2lo[o] = l;
    }
}

// ===========================================================================
// Kernel X: x -> padded channel-last split-bf16 (b, row 34, col 36, s 128)
// ===========================================================================
__global__ __launch_bounds__(256) void xprep_kernel(const float* __restrict__ x)
{
    __shared__ float sX[128 * 33];
    const int b = blockIdx.y, p = blockIdx.x, tid = threadIdx.x;
    for (int i = tid; i < 4096; i += 256) {
        int s = i >> 5, q = i & 31;
        sX[s * 33 + q] = x[(((size_t)(b * 128 + s)) * 32 + p) * 32 + q];
    }
    __syncthreads();
    for (int i = tid; i < 4096; i += 256) {
        int s = i & 127, q = i >> 7;
        float v = sX[s * 33 + q];
        __nv_bfloat16 h = __float2bfloat16(v);
        __nv_bfloat16 l = __float2bfloat16(v - __bfloat162float(h));
        size_t o = (((size_t)b * 34 + (p + 1)) * 36 + (q + 1)) * 128 + s;
        g_xhi[o] = h;
        g_xlo[o] = l;
    }
}

// ===========================================================================
// Kernel C (v3): conv GEMM with resident x-slice.
// CTA = (pxblock 8 rows, b). x-slice [10 rows][36 cols][64s hi|64s lo] pitch
// 272B loaded once per s-chunk; B fragments ldmatrix'd straight out of it at
// (u,v)-shifted offsets. Only A (W) streams per stage (18 stages, dbl buf).
// smem: XS @0 (97920) | A bufs @97920, 2 x 36864  -> 171648 B
// ===========================================================================
#define XSP    272
#define XSSZ   97920
#define APITCH 144
#define ABUF   36864
#define CSMEM  171648

__global__ __launch_bounds__(512, 1) void conv_mma_kernel(
    const float* __restrict__ xin,
    const float* __restrict__ bias,
    float* __restrict__ out)
{
    extern __shared__ char smem[];
    const uint32_t sb = smem_u32(smem);
    const int tid = threadIdx.x, wid = tid >> 5, lane = tid & 31;
    const int b = blockIdx.y, pb = blockIdx.x;   // pixel rows pb*8..pb*8+7
    const int f0 = (wid >> 2) * 32;
    const int px0 = (wid & 3) * 64;

    float d[2][8][4];
#pragma unroll
    for (int i = 0; i < 2; i++)
#pragma unroll
        for (int j = 0; j < 8; j++)
#pragma unroll
            for (int e = 0; e < 4; e++) d[i][j][e] = 0.0f;

    const uint32_t aoff = (uint32_t)((lane & 15) * APITCH + (lane >> 4) * 16);
    const uint32_t boffX = (uint32_t)(((lane & 7) + ((lane >> 4) << 3)) * XSP
                                      + ((lane >> 3) & 1) * 16);
    // per-warp B bases (pixel-block p), relative to slice origin
    uint32_t bb[4];
#pragma unroll
    for (int p = 0; p < 4; p++) {
        int px = px0 + p * 16;
        bb[p] = (uint32_t)(((px >> 5) * 36 + (px & 31)) * XSP) + boffX;
    }

    auto load_xslice = [&](int sc) {
        for (int i = tid; i < 5760; i += 512) {
            int r = i / 576, rem = i % 576;
            int c = rem >> 4, h = (rem >> 3) & 1, seg = rem & 7;
            const __nv_bfloat16* src =
                (h ? g_xlo : g_xhi) +
                (((size_t)(b * 34 + pb * 8 + r)) * 36 + c) * 128 + sc * 64 + seg * 8;
            cp16(sb + (uint32_t)((r * 36 + c) * XSP + h * 128 + seg * 16), src);
        }
        CP_COMMIT();
    };

    auto issueA = [&](int ast) {
        const int uv = ast % 9, sc = ast / 9;
        const uint32_t base = sb + XSSZ + (uint32_t)(ast & 1) * ABUF;
#pragma unroll
        for (int i = 0; i < 4; i++) {
            int c2 = i * 512 + tid;
            int half = c2 >> 10, rem = c2 & 1023, row = rem >> 3, seg = rem & 7;
            const __nv_bfloat16* src =
                (half ? g_W2lo : g_W2hi) +
                (((size_t)(b * 9 + uv) * 128 + row) * 128 + sc * 64 + seg * 8);
            cp16(base + half * 18432 + row * APITCH + seg * 16, src);
        }
        CP_COMMIT();
    };

    load_xslice(0);
    issueA(0);
    issueA(1);

    for (int ast = 0; ast < 18; ast++) {
        if (ast < 17) asm volatile("cp.async.wait_group 1;" ::: "memory");
        else          asm volatile("cp.async.wait_group 0;" ::: "memory");
        __syncthreads();

        const int uv = ast % 9;
        const int u = uv / 3, v = uv - 3 * u;
        const uint32_t uvoff = (uint32_t)((u * 36 + v) * XSP);
        const uint32_t baseA = sb + XSSZ + (uint32_t)(ast & 1) * ABUF;
        const uint32_t baseAh = baseA, baseAl = baseA + 18432;

#pragma unroll
        for (int kk = 0; kk < 4; kk++) {
            const uint32_t ko = (uint32_t)kk * 32;
            uint32_t ah[2][4], al[2][4], bf[4][4];
#pragma unroll
            for (int i = 0; i < 2; i++) {
                ldsm4(ah[i], baseAh + (f0 + i * 16) * APITCH + ko + aoff);
                ldsm4(al[i], baseAl + (f0 + i * 16) * APITCH + ko + aoff);
            }
#pragma unroll
            for (int p = 0; p < 4; p++)
                ldsm4(bf[p], sb + bb[p] + uvoff + ko);          // x hi
#pragma unroll
            for (int i = 0; i < 2; i++)
#pragma unroll
                for (int t = 0; t < 8; t++)
                    mma16816(d[i][t], ah[i], &bf[t >> 1][(t & 1) * 2]);
#pragma unroll
            for (int i = 0; i < 2; i++)
#pragma unroll
                for (int t = 0; t < 8; t++)
                    mma16816(d[i][t], al[i], &bf[t >> 1][(t & 1) * 2]);
#pragma unroll
            for (int p = 0; p < 4; p++)
                ldsm4(bf[p], sb + bb[p] + uvoff + ko + 128);    // x lo
#pragma unroll
            for (int i = 0; i < 2; i++)
#pragma unroll
                for (int t = 0; t < 8; t++)
                    mma16816(d[i][t], ah[i], &bf[t >> 1][(t & 1) * 2]);
        }
        __syncthreads();

        if (ast == 8) load_xslice(1);
        if (ast + 2 < 18) issueA(ast + 2);
    }

    // ---- epilogue: + residual + bias ----
    const int g = lane >> 2, tc = lane & 3;
#pragma unroll
    for (int i = 0; i < 2; i++) {
        const int fr0 = f0 + i * 16 + g;
        const float bv0 = __ldg(&bias[fr0]);
        const float bv1 = __ldg(&bias[fr0 + 8]);
#pragma unroll
        for (int j = 0; j < 8; j++) {
            const int pix = pb * 256 + px0 + j * 8 + tc * 2;
            {
                size_t o = ((size_t)(b * 128 + fr0)) * 1024 + pix;
                float2 xr = *reinterpret_cast<const float2*>(xin + o);
                float2 w = make_float2(d[i][j][0] + xr.x + bv0,
                                       d[i][j][1] + xr.y + bv0);
                *reinterpret_cast<float2*>(out + o) = w;
            }
            {
                size_t o = ((size_t)(b * 128 + fr0 + 8)) * 1024 + pix;
                float2 xr = *reinterpret_cast<const float2*>(xin + o);
                float2 w = make_float2(d[i][j][2] + xr.x + bv1,
                                       d[i][j][3] + xr.y + bv1);
                *reinterpret_cast<float2*>(out + o) = w;
            }
        }
    }
}

// ===========================================================================
extern "C" void kernel_launch(void* const* d_in, const int* in_sizes, int n_in,
                              void* d_out, int out_size)
{
    (void)in_sizes; (void)n_in; (void)out_size;
    const float* x     = (const float*)d_in[0];
    const float* z     = (const float*)d_in[1];
    const float* dw    = (const float*)d_in[2];
    const float* db    = (const float*)d_in[3];
    const float* gamma = (const float*)d_in[4];
    const float* beta  = (const float*)d_in[5];
    const float* bconv = (const float*)d_in[6];
    float* out = (float*)d_out;

    cudaFuncSetAttribute(hyper_mma_kernel,
                         cudaFuncAttributeMaxDynamicSharedMemorySize, HP_SMEM);
    cudaFuncSetAttribute(conv_mma_kernel,
                         cudaFuncAttributeMaxDynamicSharedMemorySize, CSMEM);

    hyper_mma_kernel<<<NB / 256, 512, HP_SMEM>>>(z, dw, db, gamma, beta);
    xprep_kernel<<<dim3(32, BATCH), 256>>>(x);
    wtrans_kernel<<<dim3(16, BATCH), 256>>>();
    conv_mma_kernel<<<dim3(4, BATCH), 512, CSMEM>>>(x, bconv, out);
}